// round 9
// baseline (speedup 1.0000x reference)
#include <cuda_runtime.h>
#include <cuda.h>
#include <cstdint>

// ---------------- scratch (no allocations allowed) ----------------
#define MAX_BLOCKS 2048
__device__ float g_partials[MAX_BLOCKS];
__device__ unsigned int g_ticket = 0;   // last block wraps it back to 0

// ---------------- small PTX helpers ----------------
__device__ __forceinline__ uint32_t smem_u32(const void* p) {
    uint32_t a;
    asm("{ .reg .u64 t; cvta.to.shared.u64 t, %1; cvt.u32.u64 %0, t; }"
        : "=r"(a) : "l"(p));
    return a;
}
#define MBARRIER_INIT(addr, cnt) \
    asm volatile("mbarrier.init.shared.b64 [%0], %1;" :: "r"(addr), "r"(cnt) : "memory")
#define MBARRIER_EXPECT_TX(addr, bytes) \
    asm volatile("mbarrier.arrive.expect_tx.shared.b64 _, [%0], %1;" :: "r"(addr), "r"(bytes) : "memory")
__device__ __forceinline__ void mbar_wait(uint32_t mbar, uint32_t parity) {
    asm volatile(
        "{\n\t"
        ".reg .pred P1;\n\t"
        "WAIT_LOOP_%=:\n\t"
        "mbarrier.try_wait.parity.acquire.cta.shared::cta.b64 P1, [%0], %1, 0x989680;\n\t"
        "@P1 bra.uni WAIT_DONE_%=;\n\t"
        "bra.uni WAIT_LOOP_%=;\n\t"
        "WAIT_DONE_%=:\n\t"
        "}"
        :: "r"(mbar), "r"(parity) : "memory");
}
// TMA tile::gather4 — fetch 4 rows (16B each, boxDim={4,1}) into SMEM (64B).
// dst MUST be 128B aligned.
__device__ __forceinline__ void tma_gather4(uint32_t dst_smem, const void* tmap,
                                            int r0, int r1, int r2, int r3,
                                            uint32_t mbar) {
    asm volatile(
        "cp.async.bulk.tensor.2d.shared::cta.global.tile::gather4.mbarrier::complete_tx::bytes "
        "[%0], [%1, {%2, %3, %4, %5, %6}], [%7];"
        :: "r"(dst_smem), "l"(tmap), "r"(0), "r"(r0), "r"(r1), "r"(r2), "r"(r3),
           "r"(mbar)
        : "memory");
}

// ---------------- shared reduction epilogue ----------------
#define REDUCE_EPILOGUE(acc, out, inv_p)                                        \
    do {                                                                        \
        _Pragma("unroll")                                                       \
        for (int off = 16; off > 0; off >>= 1)                                  \
            acc += __shfl_down_sync(0xffffffffu, acc, off);                     \
        __shared__ float warp_sums_[8];                                         \
        int lane_ = threadIdx.x & 31;                                           \
        int wid_  = threadIdx.x >> 5;                                           \
        if (lane_ == 0) warp_sums_[wid_] = acc;                                 \
        __syncthreads();                                                        \
        __shared__ bool is_last_;                                               \
        if (wid_ == 0) {                                                        \
            float v = (lane_ < 8) ? warp_sums_[lane_] : 0.0f;                   \
            _Pragma("unroll")                                                   \
            for (int off = 4; off > 0; off >>= 1)                               \
                v += __shfl_down_sync(0xffffffffu, v, off);                     \
            if (lane_ == 0) {                                                   \
                g_partials[blockIdx.x] = v;                                     \
                __threadfence();                                                \
                unsigned int done = atomicInc(&g_ticket, gridDim.x - 1);        \
                is_last_ = (done == gridDim.x - 1);                             \
            }                                                                   \
        }                                                                       \
        __syncthreads();                                                        \
        if (is_last_) {                                                         \
            double s = 0.0;                                                     \
            for (int i = threadIdx.x; i < (int)gridDim.x; i += blockDim.x)      \
                s += (double)g_partials[i];                                     \
            __shared__ double dsums_[8];                                        \
            _Pragma("unroll")                                                   \
            for (int off = 16; off > 0; off >>= 1)                              \
                s += __shfl_down_sync(0xffffffffu, s, off);                     \
            if (lane_ == 0) dsums_[wid_] = s;                                   \
            __syncthreads();                                                    \
            if (wid_ == 0) {                                                    \
                double t = (lane_ < 8) ? dsums_[lane_] : 0.0;                   \
                _Pragma("unroll")                                               \
                for (int off = 4; off > 0; off >>= 1)                           \
                    t += __shfl_down_sync(0xffffffffu, t, off);                 \
                if (lane_ == 0) out[0] = (float)(t * (double)inv_p);            \
            }                                                                   \
        }                                                                       \
    } while (0)

// ================= hybrid kernel, rate-balanced, deep TMA ring =================
// Warps 0-5 (~75% of edges): LDG gathers via L1tex/LSU pipe, 2x unrolled
//   (8 outstanding float4 gathers per thread).
// Warps 6-7 (~25% of edges): TMA gather4 via the TMA engine, 64 edges per
//   warp-batch, 4-stage ring buffer per warp (restores R7's queue depth).
#define LDG_WARPS 6
#define TMA_WARPS 2
#define TMA_STAGES 4
#define STRIDE_PER_LANE 128  // gather4 dst must be 128B aligned
#define STAGE_BYTES (32 * STRIDE_PER_LANE)   // 4096 per warp-stage

__global__ void __launch_bounds__(256)
mde_hybrid_kernel(const __grid_constant__ CUtensorMap tmap,
                  const float4* __restrict__ X,
                  const int4* __restrict__ epairs,
                  const float2* __restrict__ wpairs,
                  int npairs_ldg,          // int4 pairs in LDG region
                  int nb_tma,              // 64-edge batches in TMA region
                  const int2* __restrict__ etail,
                  const float* __restrict__ wtail,
                  int tail_lo, int tail_hi, // leftover single edges [lo, hi)
                  float* __restrict__ out, float inv_p) {
    __shared__ __align__(8)   uint64_t mbar[TMA_WARPS][TMA_STAGES];
    __shared__ __align__(128) char tbuf[TMA_WARPS][TMA_STAGES][STAGE_BYTES];

    int tid  = threadIdx.x;
    int lane = tid & 31;
    int wid  = tid >> 5;
    float acc = 0.0f;

    if (wid < LDG_WARPS) {
        // ---------- LDG path (2x unrolled for MLP) ----------
        int t = blockIdx.x * (LDG_WARPS * 32) + wid * 32 + lane;
        int stride = gridDim.x * (LDG_WARPS * 32);
        int k = t;
        for (; k + stride < npairs_ldg; k += 2 * stride) {
            int4   eA = __ldcs(&epairs[k]);
            int4   eB = __ldcs(&epairs[k + stride]);
            float2 wA = __ldcs(&wpairs[k]);
            float2 wB = __ldcs(&wpairs[k + stride]);
            float4 a0 = __ldg(&X[eA.x]);
            float4 b0 = __ldg(&X[eA.y]);
            float4 a1 = __ldg(&X[eA.z]);
            float4 b1 = __ldg(&X[eA.w]);
            float4 a2 = __ldg(&X[eB.x]);
            float4 b2 = __ldg(&X[eB.y]);
            float4 a3 = __ldg(&X[eB.z]);
            float4 b3 = __ldg(&X[eB.w]);
            float dx0 = a0.x - b0.x, dy0 = a0.y - b0.y, dz0 = a0.z - b0.z, dw0 = a0.w - b0.w;
            float dx1 = a1.x - b1.x, dy1 = a1.y - b1.y, dz1 = a1.z - b1.z, dw1 = a1.w - b1.w;
            float dx2 = a2.x - b2.x, dy2 = a2.y - b2.y, dz2 = a2.z - b2.z, dw2 = a2.w - b2.w;
            float dx3 = a3.x - b3.x, dy3 = a3.y - b3.y, dz3 = a3.z - b3.z, dw3 = a3.w - b3.w;
            acc = fmaf(wA.x, dx0 * dx0 + dy0 * dy0 + dz0 * dz0 + dw0 * dw0, acc);
            acc = fmaf(wA.y, dx1 * dx1 + dy1 * dy1 + dz1 * dz1 + dw1 * dw1, acc);
            acc = fmaf(wB.x, dx2 * dx2 + dy2 * dy2 + dz2 * dz2 + dw2 * dw2, acc);
            acc = fmaf(wB.y, dx3 * dx3 + dy3 * dy3 + dz3 * dz3 + dw3 * dw3, acc);
        }
        for (; k < npairs_ldg; k += stride) {
            int4   e = __ldcs(&epairs[k]);
            float2 w = __ldcs(&wpairs[k]);
            float4 a0 = __ldg(&X[e.x]);
            float4 b0 = __ldg(&X[e.y]);
            float4 a1 = __ldg(&X[e.z]);
            float4 b1 = __ldg(&X[e.w]);
            float dx0 = a0.x - b0.x, dy0 = a0.y - b0.y, dz0 = a0.z - b0.z, dw0 = a0.w - b0.w;
            float dx1 = a1.x - b1.x, dy1 = a1.y - b1.y, dz1 = a1.z - b1.z, dw1 = a1.w - b1.w;
            acc = fmaf(w.x, dx0 * dx0 + dy0 * dy0 + dz0 * dz0 + dw0 * dw0, acc);
            acc = fmaf(w.y, dx1 * dx1 + dy1 * dy1 + dz1 * dz1 + dw1 * dw1, acc);
        }
        // leftover single edges (at most 1)
        for (int q = tail_lo + t; q < tail_hi; q += stride) {
            int2 e = __ldg(&etail[q]);
            float4 a = __ldg(&X[e.x]);
            float4 b = __ldg(&X[e.y]);
            float dx = a.x - b.x, dy = a.y - b.y, dz = a.z - b.z, dw = a.w - b.w;
            acc = fmaf(__ldg(&wtail[q]), dx * dx + dy * dy + dz * dz + dw * dw, acc);
        }
    } else {
        // ---------- TMA gather4 path, 4-stage ring ----------
        int tw = wid - LDG_WARPS;            // 0..1
        uint32_t mb[TMA_STAGES], bufa[TMA_STAGES];
        #pragma unroll
        for (int s = 0; s < TMA_STAGES; s++) {
            mb[s]   = smem_u32(&mbar[tw][s]);
            bufa[s] = smem_u32(&tbuf[tw][s][0]) + (uint32_t)lane * STRIDE_PER_LANE;
        }
        if (lane == 0) {
            #pragma unroll
            for (int s = 0; s < TMA_STAGES; s++) MBARRIER_INIT(mb[s], 1);
            asm volatile("fence.proxy.async.shared::cta;" ::: "memory");
        }
        __syncwarp();

        int W  = gridDim.x * TMA_WARPS;
        int gw = blockIdx.x * TMA_WARPS + tw;
        int nlocal = (gw < nb_tma) ? ((nb_tma - 1 - gw) / W + 1) : 0;

        float2 wreg[TMA_STAGES];
        int ph[TMA_STAGES] = {0, 0, 0, 0};

        auto issue = [&](int bl) {
            int s = bl & (TMA_STAGES - 1);
            int gb = gw + bl * W;
            int idx = npairs_ldg + gb * 32 + lane;   // int4 index into edge array
            if (lane == 0) MBARRIER_EXPECT_TX(mb[s], 32 * 64);
            __syncwarp();
            int4 e = __ldcs(&epairs[idx]);
            wreg[s] = __ldcs(&wpairs[idx]);
            tma_gather4(bufa[s], (const void*)&tmap, e.x, e.y, e.z, e.w, mb[s]);
        };

        int npro = (nlocal < TMA_STAGES) ? nlocal : TMA_STAGES;
        for (int b = 0; b < npro; b++) issue(b);

        for (int b = 0; b < nlocal; b++) {
            int s = b & (TMA_STAGES - 1);
            mbar_wait(mb[s], ph[s]); ph[s] ^= 1;
            const float4* blk = (const float4*)__cvta_shared_to_generic(bufa[s]);
            float4 a0 = blk[0], b0 = blk[1], a1 = blk[2], b1 = blk[3];
            float2 w = wreg[s];
            float dx0 = a0.x - b0.x, dy0 = a0.y - b0.y, dz0 = a0.z - b0.z, dw0 = a0.w - b0.w;
            float dx1 = a1.x - b1.x, dy1 = a1.y - b1.y, dz1 = a1.z - b1.z, dw1 = a1.w - b1.w;
            acc = fmaf(w.x, dx0 * dx0 + dy0 * dy0 + dz0 * dz0 + dw0 * dw0, acc);
            acc = fmaf(w.y, dx1 * dx1 + dy1 * dy1 + dz1 * dz1 + dw1 * dw1, acc);
            if (b + TMA_STAGES < nlocal) issue(b + TMA_STAGES);
        }
    }

    REDUCE_EPILOGUE(acc, out, inv_p);
}

// ================= fallback LDG kernel (proven 80.6us) =================
__global__ void __launch_bounds__(256)
mde_ldg_kernel(const float4* __restrict__ X,
               const int4* __restrict__ epairs,
               const float2* __restrict__ wpairs,
               int npairs,
               const int2* __restrict__ etail,
               const float* __restrict__ wtail,
               int p,
               float* __restrict__ out, float inv_p) {
    float acc = 0.0f;
    int stride = gridDim.x * blockDim.x;
    int tid = blockIdx.x * blockDim.x + threadIdx.x;
    for (int k = tid; k < npairs; k += stride) {
        int4   e = __ldcs(&epairs[k]);
        float2 w = __ldcs(&wpairs[k]);
        float4 a0 = __ldg(&X[e.x]);
        float4 b0 = __ldg(&X[e.y]);
        float4 a1 = __ldg(&X[e.z]);
        float4 b1 = __ldg(&X[e.w]);
        float dx0 = a0.x - b0.x, dy0 = a0.y - b0.y, dz0 = a0.z - b0.z, dw0 = a0.w - b0.w;
        float dx1 = a1.x - b1.x, dy1 = a1.y - b1.y, dz1 = a1.z - b1.z, dw1 = a1.w - b1.w;
        acc = fmaf(w.x, dx0 * dx0 + dy0 * dy0 + dz0 * dz0 + dw0 * dw0, acc);
        acc = fmaf(w.y, dx1 * dx1 + dy1 * dy1 + dz1 * dz1 + dw1 * dw1, acc);
    }
    int tail_base = npairs * 2;
    for (int k = tail_base + tid; k < p; k += stride) {
        int2 e = __ldg(&etail[k]);
        float4 a = __ldg(&X[e.x]);
        float4 b = __ldg(&X[e.y]);
        float dx = a.x - b.x, dy = a.y - b.y, dz = a.z - b.z, dw = a.w - b.w;
        acc = fmaf(__ldg(&wtail[k]), dx * dx + dy * dy + dz * dz + dw * dw, acc);
    }
    REDUCE_EPILOGUE(acc, out, inv_p);
}

// ================= host =================
extern "C" void kernel_launch(void* const* d_in, const int* in_sizes, int n_in,
                              void* d_out, int out_size) {
    const float4* X     = (const float4*)d_in[0];
    const int*    edges = (const int*)d_in[1];
    const float*  w     = (const float*)d_in[2];
    float*        out   = (float*)d_out;

    int p = in_sizes[2];
    float inv_p = 1.0f / (float)p;

    // Encode gather4 tensor map for X: f32 rank-2, global [4 x n_items], box {4,1}.
    bool tma_ok = false;
    CUtensorMap tmap;
    {
        typedef CUresult (*EncodeFn)(CUtensorMap*, CUtensorMapDataType, cuuint32_t,
                                     void*, const cuuint64_t*, const cuuint64_t*,
                                     const cuuint32_t*, const cuuint32_t*,
                                     CUtensorMapInterleave, CUtensorMapSwizzle,
                                     CUtensorMapL2promotion, CUtensorMapFloatOOBfill);
        EncodeFn fn = nullptr;
        cudaDriverEntryPointQueryResult qres;
        if (cudaGetDriverEntryPointByVersion("cuTensorMapEncodeTiled", (void**)&fn,
                                             12000, cudaEnableDefault, &qres) == cudaSuccess
            && fn != nullptr) {
            cuuint64_t gdim[2] = {4ull, (cuuint64_t)(in_sizes[0] / 4)};
            cuuint64_t gstr[1] = {16ull};
            cuuint32_t box[2]  = {4u, 1u};
            cuuint32_t est[2]  = {1u, 1u};
            CUresult r = fn(&tmap, CU_TENSOR_MAP_DATA_TYPE_FLOAT32, 2, (void*)X,
                            gdim, gstr, box, est,
                            CU_TENSOR_MAP_INTERLEAVE_NONE,
                            CU_TENSOR_MAP_SWIZZLE_NONE,
                            CU_TENSOR_MAP_L2_PROMOTION_L2_128B,
                            CU_TENSOR_MAP_FLOAT_OOB_FILL_NONE);
            tma_ok = (r == CUDA_SUCCESS);
        }
    }

    if (tma_ok && p >= 512) {
        int blocks = 888;   // 148 SMs x 6 CTAs (smem ~33KB/CTA)
        // Rate-proportional split: TMA ~25% (0.148 vs 0.476 edges/cyc/SM).
        int nb_tma = (p / 4) / 64;          // 25% of edges in 64-edge batches
        int tma_edges = nb_tma * 64;
        int L = p - tma_edges;              // LDG region [0, L)
        int npairs_ldg = L / 2;
        int tail_lo = npairs_ldg * 2;       // leftover single edges in [tail_lo, L)
        mde_hybrid_kernel<<<blocks, 256>>>(tmap, X,
                                           (const int4*)edges, (const float2*)w,
                                           npairs_ldg, nb_tma,
                                           (const int2*)edges, w, tail_lo, L,
                                           out, inv_p);
    } else {
        int blocks = 1184;
        int npairs = p / 2;
        mde_ldg_kernel<<<blocks, 256>>>(X,
                                        (const int4*)edges, (const float2*)w, npairs,
                                        (const int2*)edges, w, p,
                                        out, inv_p);
    }
}

// round 10
// speedup vs baseline: 1.1091x; 1.1091x over previous
#include <cuda_runtime.h>
#include <cuda.h>
#include <cstdint>

// ---------------- scratch (no allocations allowed) ----------------
#define MAX_BLOCKS 2048
__device__ float g_partials[MAX_BLOCKS];
__device__ unsigned int g_ticket = 0;   // last block wraps it back to 0

// ---------------- small PTX helpers ----------------
__device__ __forceinline__ uint32_t smem_u32(const void* p) {
    uint32_t a;
    asm("{ .reg .u64 t; cvta.to.shared.u64 t, %1; cvt.u32.u64 %0, t; }"
        : "=r"(a) : "l"(p));
    return a;
}
#define MBARRIER_INIT(addr, cnt) \
    asm volatile("mbarrier.init.shared.b64 [%0], %1;" :: "r"(addr), "r"(cnt) : "memory")
#define MBARRIER_EXPECT_TX(addr, bytes) \
    asm volatile("mbarrier.arrive.expect_tx.shared.b64 _, [%0], %1;" :: "r"(addr), "r"(bytes) : "memory")
__device__ __forceinline__ void mbar_wait(uint32_t mbar, uint32_t parity) {
    asm volatile(
        "{\n\t"
        ".reg .pred P1;\n\t"
        "WAIT_LOOP_%=:\n\t"
        "mbarrier.try_wait.parity.acquire.cta.shared::cta.b64 P1, [%0], %1, 0x989680;\n\t"
        "@P1 bra.uni WAIT_DONE_%=;\n\t"
        "bra.uni WAIT_LOOP_%=;\n\t"
        "WAIT_DONE_%=:\n\t"
        "}"
        :: "r"(mbar), "r"(parity) : "memory");
}
// TMA tile::gather4 — fetch 4 rows (16B each, boxDim={4,1}) into SMEM (64B).
// dst MUST be 128B aligned.
__device__ __forceinline__ void tma_gather4(uint32_t dst_smem, const void* tmap,
                                            int r0, int r1, int r2, int r3,
                                            uint32_t mbar) {
    asm volatile(
        "cp.async.bulk.tensor.2d.shared::cta.global.tile::gather4.mbarrier::complete_tx::bytes "
        "[%0], [%1, {%2, %3, %4, %5, %6}], [%7];"
        :: "r"(dst_smem), "l"(tmap), "r"(0), "r"(r0), "r"(r1), "r"(r2), "r"(r3),
           "r"(mbar)
        : "memory");
}

// ---------------- shared reduction epilogue ----------------
#define REDUCE_EPILOGUE(acc, out, inv_p)                                        \
    do {                                                                        \
        _Pragma("unroll")                                                       \
        for (int off = 16; off > 0; off >>= 1)                                  \
            acc += __shfl_down_sync(0xffffffffu, acc, off);                     \
        __shared__ float warp_sums_[8];                                         \
        int lane_ = threadIdx.x & 31;                                           \
        int wid_  = threadIdx.x >> 5;                                           \
        if (lane_ == 0) warp_sums_[wid_] = acc;                                 \
        __syncthreads();                                                        \
        __shared__ bool is_last_;                                               \
        if (wid_ == 0) {                                                        \
            float v = (lane_ < 8) ? warp_sums_[lane_] : 0.0f;                   \
            _Pragma("unroll")                                                   \
            for (int off = 4; off > 0; off >>= 1)                               \
                v += __shfl_down_sync(0xffffffffu, v, off);                     \
            if (lane_ == 0) {                                                   \
                g_partials[blockIdx.x] = v;                                     \
                __threadfence();                                                \
                unsigned int done = atomicInc(&g_ticket, gridDim.x - 1);        \
                is_last_ = (done == gridDim.x - 1);                             \
            }                                                                   \
        }                                                                       \
        __syncthreads();                                                        \
        if (is_last_) {                                                         \
            double s = 0.0;                                                     \
            for (int i = threadIdx.x; i < (int)gridDim.x; i += blockDim.x)      \
                s += (double)g_partials[i];                                     \
            __shared__ double dsums_[8];                                        \
            _Pragma("unroll")                                                   \
            for (int off = 16; off > 0; off >>= 1)                              \
                s += __shfl_down_sync(0xffffffffu, s, off);                     \
            if (lane_ == 0) dsums_[wid_] = s;                                   \
            __syncthreads();                                                    \
            if (wid_ == 0) {                                                    \
                double t = (lane_ < 8) ? dsums_[lane_] : 0.0;                   \
                _Pragma("unroll")                                               \
                for (int off = 4; off > 0; off >>= 1)                           \
                    t += __shfl_down_sync(0xffffffffu, t, off);                 \
                if (lane_ == 0) out[0] = (float)(t * (double)inv_p);            \
            }                                                                   \
        }                                                                       \
    } while (0)

// ================= hybrid kernel: static 4-stage TMA ring =================
// Warps 0-5 (~75% of edges): LDG gathers (L1tex floor path, R8-proven loop).
// Warps 6-7 (~25% of edges): TMA gather4, 64 edges per warp-batch, 4-stage ring
//   with ALL stage state in individually named registers (no indexed arrays ->
//   no local-memory spills, the R9 failure mode).
#define LDG_WARPS 6
#define TMA_WARPS 2
#define STRIDE_PER_LANE 128  // gather4 dst must be 128B aligned
#define STAGE_BYTES (32 * STRIDE_PER_LANE)   // 4096 per warp-stage

__global__ void __launch_bounds__(256)
mde_hybrid_kernel(const __grid_constant__ CUtensorMap tmap,
                  const float4* __restrict__ X,
                  const int4* __restrict__ epairs,
                  const float2* __restrict__ wpairs,
                  int npairs_ldg,          // int4 pairs in LDG region
                  int nb_tma,              // 64-edge batches in TMA region
                  const int2* __restrict__ etail,
                  const float* __restrict__ wtail,
                  int tail_lo, int tail_hi, // leftover single edges [lo, hi)
                  float* __restrict__ out, float inv_p) {
    __shared__ __align__(8)   uint64_t mbar[TMA_WARPS][4];
    __shared__ __align__(128) char tbuf[TMA_WARPS][4][STAGE_BYTES];

    int tid  = threadIdx.x;
    int lane = tid & 31;
    int wid  = tid >> 5;
    float acc = 0.0f;

    if (wid < LDG_WARPS) {
        // ---------- LDG path (R8-proven) ----------
        int t = blockIdx.x * (LDG_WARPS * 32) + wid * 32 + lane;
        int stride = gridDim.x * (LDG_WARPS * 32);
        for (int k = t; k < npairs_ldg; k += stride) {
            int4   e = __ldcs(&epairs[k]);
            float2 w = __ldcs(&wpairs[k]);
            float4 a0 = __ldg(&X[e.x]);
            float4 b0 = __ldg(&X[e.y]);
            float4 a1 = __ldg(&X[e.z]);
            float4 b1 = __ldg(&X[e.w]);
            float dx0 = a0.x - b0.x, dy0 = a0.y - b0.y, dz0 = a0.z - b0.z, dw0 = a0.w - b0.w;
            float dx1 = a1.x - b1.x, dy1 = a1.y - b1.y, dz1 = a1.z - b1.z, dw1 = a1.w - b1.w;
            acc = fmaf(w.x, dx0 * dx0 + dy0 * dy0 + dz0 * dz0 + dw0 * dw0, acc);
            acc = fmaf(w.y, dx1 * dx1 + dy1 * dy1 + dz1 * dz1 + dw1 * dw1, acc);
        }
        for (int q = tail_lo + t; q < tail_hi; q += stride) {
            int2 e = __ldg(&etail[q]);
            float4 a = __ldg(&X[e.x]);
            float4 b = __ldg(&X[e.y]);
            float dx = a.x - b.x, dy = a.y - b.y, dz = a.z - b.z, dw = a.w - b.w;
            acc = fmaf(__ldg(&wtail[q]), dx * dx + dy * dy + dz * dz + dw * dw, acc);
        }
    } else {
        // ---------- TMA gather4 path, static 4-stage ring ----------
        int tw = wid - LDG_WARPS;            // 0..1
        uint32_t mb0 = smem_u32(&mbar[tw][0]);
        uint32_t mb1 = smem_u32(&mbar[tw][1]);
        uint32_t mb2 = smem_u32(&mbar[tw][2]);
        uint32_t mb3 = smem_u32(&mbar[tw][3]);
        uint32_t lofs = (uint32_t)lane * STRIDE_PER_LANE;
        uint32_t buf0 = smem_u32(&tbuf[tw][0][0]) + lofs;
        uint32_t buf1 = smem_u32(&tbuf[tw][1][0]) + lofs;
        uint32_t buf2 = smem_u32(&tbuf[tw][2][0]) + lofs;
        uint32_t buf3 = smem_u32(&tbuf[tw][3][0]) + lofs;
        if (lane == 0) {
            MBARRIER_INIT(mb0, 1);
            MBARRIER_INIT(mb1, 1);
            MBARRIER_INIT(mb2, 1);
            MBARRIER_INIT(mb3, 1);
            asm volatile("fence.proxy.async.shared::cta;" ::: "memory");
        }
        __syncwarp();

        int W  = gridDim.x * TMA_WARPS;
        int gw = blockIdx.x * TMA_WARPS + tw;
        int nlocal = (gw < nb_tma) ? ((nb_tma - 1 - gw) / W + 1) : 0;

        float2 w0, w1, w2, w3;
        int ph0 = 0, ph1 = 0, ph2 = 0, ph3 = 0;

        auto issue = [&](int bl, uint32_t mb, uint32_t bufaddr, float2& wreg) {
            int gb = gw + bl * W;
            int idx = npairs_ldg + gb * 32 + lane;   // int4 index into edge array
            if (lane == 0) MBARRIER_EXPECT_TX(mb, 32 * 64);
            __syncwarp();
            int4 e = __ldcs(&epairs[idx]);
            wreg = __ldcs(&wpairs[idx]);
            tma_gather4(bufaddr, (const void*)&tmap, e.x, e.y, e.z, e.w, mb);
        };
        auto consume = [&](uint32_t bufaddr, float2 w) {
            const float4* blk = (const float4*)__cvta_shared_to_generic(bufaddr);
            float4 a0 = blk[0], b0 = blk[1], a1 = blk[2], b1 = blk[3];
            float dx0 = a0.x - b0.x, dy0 = a0.y - b0.y, dz0 = a0.z - b0.z, dw0 = a0.w - b0.w;
            float dx1 = a1.x - b1.x, dy1 = a1.y - b1.y, dz1 = a1.z - b1.z, dw1 = a1.w - b1.w;
            acc = fmaf(w.x, dx0 * dx0 + dy0 * dy0 + dz0 * dz0 + dw0 * dw0, acc);
            acc = fmaf(w.y, dx1 * dx1 + dy1 * dy1 + dz1 * dz1 + dw1 * dw1, acc);
        };

        // Prologue: fill up to 4 stages.
        if (nlocal > 0) issue(0, mb0, buf0, w0);
        if (nlocal > 1) issue(1, mb1, buf1, w1);
        if (nlocal > 2) issue(2, mb2, buf2, w2);
        if (nlocal > 3) issue(3, mb3, buf3, w3);

        // Main loop: 4 batches per iteration, all stage indices static.
        int b = 0;
        for (; b + 4 <= nlocal; b += 4) {
            mbar_wait(mb0, ph0); ph0 ^= 1;
            consume(buf0, w0);
            if (b + 4 < nlocal) issue(b + 4, mb0, buf0, w0);

            mbar_wait(mb1, ph1); ph1 ^= 1;
            consume(buf1, w1);
            if (b + 5 < nlocal) issue(b + 5, mb1, buf1, w1);

            mbar_wait(mb2, ph2); ph2 ^= 1;
            consume(buf2, w2);
            if (b + 6 < nlocal) issue(b + 6, mb2, buf2, w2);

            mbar_wait(mb3, ph3); ph3 ^= 1;
            consume(buf3, w3);
            if (b + 7 < nlocal) issue(b + 7, mb3, buf3, w3);
        }
        // Remainder (<=3 batches, already issued; stages rotate from 0).
        if (b < nlocal) { mbar_wait(mb0, ph0); consume(buf0, w0); b++; }
        if (b < nlocal) { mbar_wait(mb1, ph1); consume(buf1, w1); b++; }
        if (b < nlocal) { mbar_wait(mb2, ph2); consume(buf2, w2); b++; }
    }

    REDUCE_EPILOGUE(acc, out, inv_p);
}

// ================= fallback LDG kernel (proven 80.6us) =================
__global__ void __launch_bounds__(256)
mde_ldg_kernel(const float4* __restrict__ X,
               const int4* __restrict__ epairs,
               const float2* __restrict__ wpairs,
               int npairs,
               const int2* __restrict__ etail,
               const float* __restrict__ wtail,
               int p,
               float* __restrict__ out, float inv_p) {
    float acc = 0.0f;
    int stride = gridDim.x * blockDim.x;
    int tid = blockIdx.x * blockDim.x + threadIdx.x;
    for (int k = tid; k < npairs; k += stride) {
        int4   e = __ldcs(&epairs[k]);
        float2 w = __ldcs(&wpairs[k]);
        float4 a0 = __ldg(&X[e.x]);
        float4 b0 = __ldg(&X[e.y]);
        float4 a1 = __ldg(&X[e.z]);
        float4 b1 = __ldg(&X[e.w]);
        float dx0 = a0.x - b0.x, dy0 = a0.y - b0.y, dz0 = a0.z - b0.z, dw0 = a0.w - b0.w;
        float dx1 = a1.x - b1.x, dy1 = a1.y - b1.y, dz1 = a1.z - b1.z, dw1 = a1.w - b1.w;
        acc = fmaf(w.x, dx0 * dx0 + dy0 * dy0 + dz0 * dz0 + dw0 * dw0, acc);
        acc = fmaf(w.y, dx1 * dx1 + dy1 * dy1 + dz1 * dz1 + dw1 * dw1, acc);
    }
    int tail_base = npairs * 2;
    for (int k = tail_base + tid; k < p; k += stride) {
        int2 e = __ldg(&etail[k]);
        float4 a = __ldg(&X[e.x]);
        float4 b = __ldg(&X[e.y]);
        float dx = a.x - b.x, dy = a.y - b.y, dz = a.z - b.z, dw = a.w - b.w;
        acc = fmaf(__ldg(&wtail[k]), dx * dx + dy * dy + dz * dz + dw * dw, acc);
    }
    REDUCE_EPILOGUE(acc, out, inv_p);
}

// ================= host =================
extern "C" void kernel_launch(void* const* d_in, const int* in_sizes, int n_in,
                              void* d_out, int out_size) {
    const float4* X     = (const float4*)d_in[0];
    const int*    edges = (const int*)d_in[1];
    const float*  w     = (const float*)d_in[2];
    float*        out   = (float*)d_out;

    int p = in_sizes[2];
    float inv_p = 1.0f / (float)p;

    // Encode gather4 tensor map for X: f32 rank-2, global [4 x n_items], box {4,1}.
    bool tma_ok = false;
    CUtensorMap tmap;
    {
        typedef CUresult (*EncodeFn)(CUtensorMap*, CUtensorMapDataType, cuuint32_t,
                                     void*, const cuuint64_t*, const cuuint64_t*,
                                     const cuuint32_t*, const cuuint32_t*,
                                     CUtensorMapInterleave, CUtensorMapSwizzle,
                                     CUtensorMapL2promotion, CUtensorMapFloatOOBfill);
        EncodeFn fn = nullptr;
        cudaDriverEntryPointQueryResult qres;
        if (cudaGetDriverEntryPointByVersion("cuTensorMapEncodeTiled", (void**)&fn,
                                             12000, cudaEnableDefault, &qres) == cudaSuccess
            && fn != nullptr) {
            cuuint64_t gdim[2] = {4ull, (cuuint64_t)(in_sizes[0] / 4)};
            cuuint64_t gstr[1] = {16ull};
            cuuint32_t box[2]  = {4u, 1u};
            cuuint32_t est[2]  = {1u, 1u};
            CUresult r = fn(&tmap, CU_TENSOR_MAP_DATA_TYPE_FLOAT32, 2, (void*)X,
                            gdim, gstr, box, est,
                            CU_TENSOR_MAP_INTERLEAVE_NONE,
                            CU_TENSOR_MAP_SWIZZLE_NONE,
                            CU_TENSOR_MAP_L2_PROMOTION_L2_128B,
                            CU_TENSOR_MAP_FLOAT_OOB_FILL_NONE);
            tma_ok = (r == CUDA_SUCCESS);
        }
    }

    if (tma_ok && p >= 512) {
        int blocks = 888;   // 148 SMs x 6 CTAs (smem ~33KB/CTA)
        // Rate-proportional split: TMA ~25% (0.148 vs 0.476 edges/cyc/SM).
        int nb_tma = (p / 4) / 64;          // 25% of edges in 64-edge batches
        int tma_edges = nb_tma * 64;
        int L = p - tma_edges;              // LDG region [0, L)
        int npairs_ldg = L / 2;
        int tail_lo = npairs_ldg * 2;       // leftover single edges in [tail_lo, L)
        mde_hybrid_kernel<<<blocks, 256>>>(tmap, X,
                                           (const int4*)edges, (const float2*)w,
                                           npairs_ldg, nb_tma,
                                           (const int2*)edges, w, tail_lo, L,
                                           out, inv_p);
    } else {
        int blocks = 1184;
        int npairs = p / 2;
        mde_ldg_kernel<<<blocks, 256>>>(X,
                                        (const int4*)edges, (const float2*)w, npairs,
                                        (const int2*)edges, w, p,
                                        out, inv_p);
    }
}

// round 11
// speedup vs baseline: 1.1421x; 1.0298x over previous
#include <cuda_runtime.h>
#include <cuda.h>
#include <cstdint>

// ---------------- scratch (no allocations allowed) ----------------
#define MAX_BLOCKS 2048
__device__ float g_partials[MAX_BLOCKS];
__device__ unsigned int g_ticket = 0;   // last block wraps it back to 0

// ---------------- small PTX helpers ----------------
__device__ __forceinline__ uint32_t smem_u32(const void* p) {
    uint32_t a;
    asm("{ .reg .u64 t; cvta.to.shared.u64 t, %1; cvt.u32.u64 %0, t; }"
        : "=r"(a) : "l"(p));
    return a;
}
#define MBARRIER_INIT(addr, cnt) \
    asm volatile("mbarrier.init.shared.b64 [%0], %1;" :: "r"(addr), "r"(cnt) : "memory")
#define MBARRIER_EXPECT_TX(addr, bytes) \
    asm volatile("mbarrier.arrive.expect_tx.shared.b64 _, [%0], %1;" :: "r"(addr), "r"(bytes) : "memory")
__device__ __forceinline__ void mbar_wait(uint32_t mbar, uint32_t parity) {
    asm volatile(
        "{\n\t"
        ".reg .pred P1;\n\t"
        "WAIT_LOOP_%=:\n\t"
        "mbarrier.try_wait.parity.acquire.cta.shared::cta.b64 P1, [%0], %1, 0x989680;\n\t"
        "@P1 bra.uni WAIT_DONE_%=;\n\t"
        "bra.uni WAIT_LOOP_%=;\n\t"
        "WAIT_DONE_%=:\n\t"
        "}"
        :: "r"(mbar), "r"(parity) : "memory");
}
// TMA tile::gather4 — fetch 4 rows (16B each, boxDim={4,1}) into SMEM (64B).
// dst MUST be 128B aligned.
__device__ __forceinline__ void tma_gather4(uint32_t dst_smem, const void* tmap,
                                            int r0, int r1, int r2, int r3,
                                            uint32_t mbar) {
    asm volatile(
        "cp.async.bulk.tensor.2d.shared::cta.global.tile::gather4.mbarrier::complete_tx::bytes "
        "[%0], [%1, {%2, %3, %4, %5, %6}], [%7];"
        :: "r"(dst_smem), "l"(tmap), "r"(0), "r"(r0), "r"(r1), "r"(r2), "r"(r3),
           "r"(mbar)
        : "memory");
}

// ---------------- shared reduction epilogue ----------------
#define REDUCE_EPILOGUE(acc, out, inv_p)                                        \
    do {                                                                        \
        _Pragma("unroll")                                                       \
        for (int off = 16; off > 0; off >>= 1)                                  \
            acc += __shfl_down_sync(0xffffffffu, acc, off);                     \
        __shared__ float warp_sums_[8];                                         \
        int lane_ = threadIdx.x & 31;                                           \
        int wid_  = threadIdx.x >> 5;                                           \
        if (lane_ == 0) warp_sums_[wid_] = acc;                                 \
        __syncthreads();                                                        \
        __shared__ bool is_last_;                                               \
        if (wid_ == 0) {                                                        \
            float v = (lane_ < 8) ? warp_sums_[lane_] : 0.0f;                   \
            _Pragma("unroll")                                                   \
            for (int off = 4; off > 0; off >>= 1)                               \
                v += __shfl_down_sync(0xffffffffu, v, off);                     \
            if (lane_ == 0) {                                                   \
                g_partials[blockIdx.x] = v;                                     \
                __threadfence();                                                \
                unsigned int done = atomicInc(&g_ticket, gridDim.x - 1);        \
                is_last_ = (done == gridDim.x - 1);                             \
            }                                                                   \
        }                                                                       \
        __syncthreads();                                                        \
        if (is_last_) {                                                         \
            double s = 0.0;                                                     \
            for (int i = threadIdx.x; i < (int)gridDim.x; i += blockDim.x)      \
                s += (double)g_partials[i];                                     \
            __shared__ double dsums_[8];                                        \
            _Pragma("unroll")                                                   \
            for (int off = 16; off > 0; off >>= 1)                              \
                s += __shfl_down_sync(0xffffffffu, s, off);                     \
            if (lane_ == 0) dsums_[wid_] = s;                                   \
            __syncthreads();                                                    \
            if (wid_ == 0) {                                                    \
                double t = (lane_ < 8) ? dsums_[lane_] : 0.0;                   \
                _Pragma("unroll")                                               \
                for (int off = 4; off > 0; off >>= 1)                           \
                    t += __shfl_down_sync(0xffffffffu, t, off);                 \
                if (lane_ == 0) out[0] = (float)(t * (double)inv_p);            \
            }                                                                   \
        }                                                                       \
    } while (0)

// ================= hybrid kernel (R7 structure, 76/24 split) =================
// Warps 0-3 (~76% of edges): LDG gathers — 4 warps suffice for the per-SM
//   L1tex wavefront floor (0.476 edges/cyc/SM, measured in R7).
// Warps 4-7 (~24% of edges): TMA gather4, 64 edges per warp-batch, 2-stage
//   double buffer. 24 issuing warps/SM saturate the UTMALDG issue cap
//   (~13.5 cyc/descriptor/SM -> 0.148 edges/cyc/SM, measured in R7).
#define LDG_WARPS 4
#define TMA_WARPS 4
#define STRIDE_PER_LANE 128  // gather4 dst must be 128B aligned
#define STAGE_BYTES (32 * STRIDE_PER_LANE)   // 4096 per warp-stage

__global__ void __launch_bounds__(256)
mde_hybrid_kernel(const __grid_constant__ CUtensorMap tmap,
                  const float4* __restrict__ X,
                  const int4* __restrict__ epairs,
                  const float2* __restrict__ wpairs,
                  int npairs_ldg,          // int4 pairs in LDG region
                  int nb_tma,              // 64-edge batches in TMA region
                  const int2* __restrict__ etail,
                  const float* __restrict__ wtail,
                  int tail_lo, int tail_hi, // leftover single edges [lo, hi)
                  float* __restrict__ out, float inv_p) {
    __shared__ __align__(8)   uint64_t mbar[TMA_WARPS * 2];
    __shared__ __align__(128) char tbuf[TMA_WARPS][2][STAGE_BYTES];

    int tid  = threadIdx.x;
    int lane = tid & 31;
    int wid  = tid >> 5;
    float acc = 0.0f;

    if (wid < LDG_WARPS) {
        // ---------- LDG path ----------
        int t = blockIdx.x * (LDG_WARPS * 32) + wid * 32 + lane;
        int stride = gridDim.x * (LDG_WARPS * 32);
        for (int k = t; k < npairs_ldg; k += stride) {
            int4   e = __ldcs(&epairs[k]);
            float2 w = __ldcs(&wpairs[k]);
            float4 a0 = __ldg(&X[e.x]);
            float4 b0 = __ldg(&X[e.y]);
            float4 a1 = __ldg(&X[e.z]);
            float4 b1 = __ldg(&X[e.w]);
            float dx0 = a0.x - b0.x, dy0 = a0.y - b0.y, dz0 = a0.z - b0.z, dw0 = a0.w - b0.w;
            float dx1 = a1.x - b1.x, dy1 = a1.y - b1.y, dz1 = a1.z - b1.z, dw1 = a1.w - b1.w;
            acc = fmaf(w.x, dx0 * dx0 + dy0 * dy0 + dz0 * dz0 + dw0 * dw0, acc);
            acc = fmaf(w.y, dx1 * dx1 + dy1 * dy1 + dz1 * dz1 + dw1 * dw1, acc);
        }
        // leftover single edges (at most 1)
        for (int q = tail_lo + t; q < tail_hi; q += stride) {
            int2 e = __ldg(&etail[q]);
            float4 a = __ldg(&X[e.x]);
            float4 b = __ldg(&X[e.y]);
            float dx = a.x - b.x, dy = a.y - b.y, dz = a.z - b.z, dw = a.w - b.w;
            acc = fmaf(__ldg(&wtail[q]), dx * dx + dy * dy + dz * dz + dw * dw, acc);
        }
    } else {
        // ---------- TMA gather4 path (R7-proven 2-stage double buffer) ----------
        int tw = wid - LDG_WARPS;            // 0..3
        uint32_t mb0 = smem_u32(&mbar[tw * 2 + 0]);
        uint32_t mb1 = smem_u32(&mbar[tw * 2 + 1]);
        uint32_t buf0 = smem_u32(&tbuf[tw][0][0]) + (uint32_t)lane * STRIDE_PER_LANE;
        uint32_t buf1 = smem_u32(&tbuf[tw][1][0]) + (uint32_t)lane * STRIDE_PER_LANE;
        if (lane == 0) {
            MBARRIER_INIT(mb0, 1);
            MBARRIER_INIT(mb1, 1);
            asm volatile("fence.proxy.async.shared::cta;" ::: "memory");
        }
        __syncwarp();

        int W  = gridDim.x * TMA_WARPS;
        int gw = blockIdx.x * TMA_WARPS + tw;
        int nlocal = (gw < nb_tma) ? ((nb_tma - 1 - gw) / W + 1) : 0;

        float2 w0, w1;
        auto issue = [&](int bl, uint32_t mb, uint32_t bufaddr, float2& wreg) {
            int gb = gw + bl * W;
            int idx = npairs_ldg + gb * 32 + lane;   // int4 index into edge array
            if (lane == 0) MBARRIER_EXPECT_TX(mb, 32 * 64);
            __syncwarp();
            int4 e = __ldcs(&epairs[idx]);
            wreg = __ldcs(&wpairs[idx]);
            tma_gather4(bufaddr, (const void*)&tmap, e.x, e.y, e.z, e.w, mb);
        };
        auto consume = [&](uint32_t bufaddr, float2 w) {
            const float4* blk = (const float4*)__cvta_shared_to_generic(bufaddr);
            float4 a0 = blk[0], b0 = blk[1], a1 = blk[2], b1 = blk[3];
            float dx0 = a0.x - b0.x, dy0 = a0.y - b0.y, dz0 = a0.z - b0.z, dw0 = a0.w - b0.w;
            float dx1 = a1.x - b1.x, dy1 = a1.y - b1.y, dz1 = a1.z - b1.z, dw1 = a1.w - b1.w;
            acc = fmaf(w.x, dx0 * dx0 + dy0 * dy0 + dz0 * dz0 + dw0 * dw0, acc);
            acc = fmaf(w.y, dx1 * dx1 + dy1 * dy1 + dz1 * dz1 + dw1 * dw1, acc);
        };

        if (nlocal > 0) issue(0, mb0, buf0, w0);
        int ph0 = 0, ph1 = 0, b = 0;
        while (b < nlocal) {
            if (b + 1 < nlocal) issue(b + 1, mb1, buf1, w1);
            mbar_wait(mb0, ph0); ph0 ^= 1;
            consume(buf0, w0);
            if (++b >= nlocal) break;
            if (b + 1 < nlocal) issue(b + 1, mb0, buf0, w0);
            mbar_wait(mb1, ph1); ph1 ^= 1;
            consume(buf1, w1);
            ++b;
        }
    }

    REDUCE_EPILOGUE(acc, out, inv_p);
}

// ================= fallback LDG kernel (proven 80.6us) =================
__global__ void __launch_bounds__(256)
mde_ldg_kernel(const float4* __restrict__ X,
               const int4* __restrict__ epairs,
               const float2* __restrict__ wpairs,
               int npairs,
               const int2* __restrict__ etail,
               const float* __restrict__ wtail,
               int p,
               float* __restrict__ out, float inv_p) {
    float acc = 0.0f;
    int stride = gridDim.x * blockDim.x;
    int tid = blockIdx.x * blockDim.x + threadIdx.x;
    for (int k = tid; k < npairs; k += stride) {
        int4   e = __ldcs(&epairs[k]);
        float2 w = __ldcs(&wpairs[k]);
        float4 a0 = __ldg(&X[e.x]);
        float4 b0 = __ldg(&X[e.y]);
        float4 a1 = __ldg(&X[e.z]);
        float4 b1 = __ldg(&X[e.w]);
        float dx0 = a0.x - b0.x, dy0 = a0.y - b0.y, dz0 = a0.z - b0.z, dw0 = a0.w - b0.w;
        float dx1 = a1.x - b1.x, dy1 = a1.y - b1.y, dz1 = a1.z - b1.z, dw1 = a1.w - b1.w;
        acc = fmaf(w.x, dx0 * dx0 + dy0 * dy0 + dz0 * dz0 + dw0 * dw0, acc);
        acc = fmaf(w.y, dx1 * dx1 + dy1 * dy1 + dz1 * dz1 + dw1 * dw1, acc);
    }
    int tail_base = npairs * 2;
    for (int k = tail_base + tid; k < p; k += stride) {
        int2 e = __ldg(&etail[k]);
        float4 a = __ldg(&X[e.x]);
        float4 b = __ldg(&X[e.y]);
        float dx = a.x - b.x, dy = a.y - b.y, dz = a.z - b.z, dw = a.w - b.w;
        acc = fmaf(__ldg(&wtail[k]), dx * dx + dy * dy + dz * dz + dw * dw, acc);
    }
    REDUCE_EPILOGUE(acc, out, inv_p);
}

// ================= host =================
extern "C" void kernel_launch(void* const* d_in, const int* in_sizes, int n_in,
                              void* d_out, int out_size) {
    const float4* X     = (const float4*)d_in[0];
    const int*    edges = (const int*)d_in[1];
    const float*  w     = (const float*)d_in[2];
    float*        out   = (float*)d_out;

    int p = in_sizes[2];
    float inv_p = 1.0f / (float)p;

    // Encode gather4 tensor map for X: f32 rank-2, global [4 x n_items], box {4,1}.
    bool tma_ok = false;
    CUtensorMap tmap;
    {
        typedef CUresult (*EncodeFn)(CUtensorMap*, CUtensorMapDataType, cuuint32_t,
                                     void*, const cuuint64_t*, const cuuint64_t*,
                                     const cuuint32_t*, const cuuint32_t*,
                                     CUtensorMapInterleave, CUtensorMapSwizzle,
                                     CUtensorMapL2promotion, CUtensorMapFloatOOBfill);
        EncodeFn fn = nullptr;
        cudaDriverEntryPointQueryResult qres;
        if (cudaGetDriverEntryPointByVersion("cuTensorMapEncodeTiled", (void**)&fn,
                                             12000, cudaEnableDefault, &qres) == cudaSuccess
            && fn != nullptr) {
            cuuint64_t gdim[2] = {4ull, (cuuint64_t)(in_sizes[0] / 4)};
            cuuint64_t gstr[1] = {16ull};
            cuuint32_t box[2]  = {4u, 1u};
            cuuint32_t est[2]  = {1u, 1u};
            CUresult r = fn(&tmap, CU_TENSOR_MAP_DATA_TYPE_FLOAT32, 2, (void*)X,
                            gdim, gstr, box, est,
                            CU_TENSOR_MAP_INTERLEAVE_NONE,
                            CU_TENSOR_MAP_SWIZZLE_NONE,
                            CU_TENSOR_MAP_L2_PROMOTION_L2_128B,
                            CU_TENSOR_MAP_FLOAT_OOB_FILL_NONE);
            tma_ok = (r == CUDA_SUCCESS);
        }
    }

    if (tma_ok && p >= 1024) {
        int blocks = 888;   // 148 SMs x 6 CTAs (smem ~33KB/CTA)
        // Rate-proportional split: LDG 0.476 vs TMA 0.148 edges/cyc/SM
        // (both measured in R7 running concurrently) -> TMA gets ~24%.
        long long tma_share = ((long long)p * 24) / 100;
        int nb_tma = (int)(tma_share / 64);
        int tma_edges = nb_tma * 64;
        int L = p - tma_edges;              // LDG region [0, L)
        int npairs_ldg = L / 2;
        int tail_lo = npairs_ldg * 2;       // leftover single edges in [tail_lo, L)
        mde_hybrid_kernel<<<blocks, 256>>>(tmap, X,
                                           (const int4*)edges, (const float2*)w,
                                           npairs_ldg, nb_tma,
                                           (const int2*)edges, w, tail_lo, L,
                                           out, inv_p);
    } else {
        int blocks = 1184;
        int npairs = p / 2;
        mde_ldg_kernel<<<blocks, 256>>>(X,
                                        (const int4*)edges, (const float2*)w, npairs,
                                        (const int2*)edges, w, p,
                                        out, inv_p);
    }
}